// round 3
// baseline (speedup 1.0000x reference)
#include <cuda_runtime.h>

// Problem: RelationalModule. Inputs (metadata order):
//  0 x_img (64*40*40 f32)  1 W0 (130*32)  2 b0 (32)
//  3 W1 (32*32)  4 b1 (32)  5 W2 (32*32)  6 b2 (32)
//  7 Wp (32*32)  8 bp (32)  9 Wo (32*32) 10 bo (32)
// Output: 32 f32.

#define N_PIX 1600
#define CCH   64
#define HID   32
#define NDUO  (N_PIX * (N_PIX / 2))   // 1,280,000 pair-duos (2 pairs each)
#define NBLK  296
#define NTHR  256

__device__ __align__(16) float g_a[N_PIX * HID];
__device__ __align__(16) float g_b[N_PIX * HID];      // includes +b0
__device__ __align__(16) float g_part[NBLK * HID];

// ---------------------------------------------------------------------------
// packed f32x2 FMA: acc.lo += a.lo*b.lo ; acc.hi += a.hi*b.hi  (one FFMA2)
// ---------------------------------------------------------------------------
__device__ __forceinline__ void fma2(float2& acc, float2 a, float2 b) {
    asm volatile("fma.rn.f32x2 %0, %1, %2, %0;"
        : "+l"(reinterpret_cast<unsigned long long&>(acc))
        : "l"(reinterpret_cast<unsigned long long&>(a)),
          "l"(reinterpret_cast<unsigned long long&>(b)));
}

// ---------------------------------------------------------------------------
// Phase 0: a[n,k] = sum_ch x[ch,n]*W0[ch,k] + n*W0[64,k]
//          b[n,k] = sum_ch x[ch,n]*W0[65+ch,k] + n*W0[129,k] + b0[k]
// ---------------------------------------------------------------------------
__global__ void precompute_ab(const float* __restrict__ x,
                              const float* __restrict__ W0,
                              const float* __restrict__ b0) {
    int gid = blockIdx.x * blockDim.x + threadIdx.x;
    if (gid >= N_PIX * HID) return;
    int n = gid >> 5;
    int k = gid & 31;
    float fa = 0.f, fb = 0.f;
#pragma unroll 8
    for (int ch = 0; ch < CCH; ch++) {
        float xv = x[ch * N_PIX + n];
        fa = fmaf(xv, W0[ch * HID + k], fa);
        fb = fmaf(xv, W0[(CCH + 1 + ch) * HID + k], fb);
    }
    float cf = (float)n;
    fa = fmaf(cf, W0[CCH * HID + k], fa);
    fb = fmaf(cf, W0[(2 * CCH + 1) * HID + k], fb);
    g_a[gid] = fa;
    g_b[gid] = fb + b0[k];
}

// ---------------------------------------------------------------------------
// Phase 1: the 2.56M-pair MLP, 2 pairs packed per thread via f32x2.
// Each thread: h0 = relu(a_j + (b_i+b0)); h1 = relu(h0@W1+b1);
//              h2 = relu(h1@W2+b2); acc += h2 (both lanes).
// Weights pre-duplicated {w,w} in shared; LDS.128 feeds 2 FFMA2s.
// ---------------------------------------------------------------------------
__global__ void __launch_bounds__(NTHR, 1)
pair_kernel(const float* __restrict__ W1, const float* __restrict__ b1,
            const float* __restrict__ W2, const float* __restrict__ b2) {
    __shared__ __align__(16) float2 sW1[HID * HID];
    __shared__ __align__(16) float2 sW2[HID * HID];
    __shared__ float sB1[HID], sB2[HID];
    __shared__ float sRed[(NTHR / 32) * HID];

    int tid = threadIdx.x;
    for (int idx = tid; idx < HID * HID; idx += NTHR) {
        float w1 = W1[idx]; sW1[idx] = make_float2(w1, w1);
        float w2 = W2[idx]; sW2[idx] = make_float2(w2, w2);
    }
    if (tid < HID) { sB1[tid] = b1[tid]; sB2[tid] = b2[tid]; }
    __syncthreads();

    float acc[HID];
#pragma unroll
    for (int m = 0; m < HID; m++) acc[m] = 0.f;

    const int total = NBLK * NTHR;
    for (int p = blockIdx.x * NTHR + tid; p < NDUO; p += total) {
        int i  = p / (N_PIX / 2);
        int jj = p - i * (N_PIX / 2);
        int j0 = jj * 2;
        const float4* A0 = reinterpret_cast<const float4*>(g_a + j0 * HID);
        const float4* A1 = reinterpret_cast<const float4*>(g_a + (j0 + 1) * HID);
        const float4* B  = reinterpret_cast<const float4*>(g_b + i * HID);

        float2 h0[HID];
#pragma unroll
        for (int q = 0; q < 8; q++) {
            float4 a0 = A0[q], a1 = A1[q], bv = B[q];
            h0[4 * q + 0] = make_float2(fmaxf(a0.x + bv.x, 0.f), fmaxf(a1.x + bv.x, 0.f));
            h0[4 * q + 1] = make_float2(fmaxf(a0.y + bv.y, 0.f), fmaxf(a1.y + bv.y, 0.f));
            h0[4 * q + 2] = make_float2(fmaxf(a0.z + bv.z, 0.f), fmaxf(a1.z + bv.z, 0.f));
            h0[4 * q + 3] = make_float2(fmaxf(a0.w + bv.w, 0.f), fmaxf(a1.w + bv.w, 0.f));
        }

        // layer 1
        float2 h1[HID];
#pragma unroll
        for (int m = 0; m < HID; m++) { float t = sB1[m]; h1[m] = make_float2(t, t); }
#pragma unroll
        for (int k = 0; k < HID; k++) {
            const float4* wr = reinterpret_cast<const float4*>(sW1 + k * HID);
            float2 hk = h0[k];
#pragma unroll
            for (int m4 = 0; m4 < 16; m4++) {
                float4 ww = wr[m4];
                fma2(h1[2 * m4 + 0], hk, make_float2(ww.x, ww.y));
                fma2(h1[2 * m4 + 1], hk, make_float2(ww.z, ww.w));
            }
        }
#pragma unroll
        for (int m = 0; m < HID; m++) {
            h1[m].x = fmaxf(h1[m].x, 0.f);
            h1[m].y = fmaxf(h1[m].y, 0.f);
        }

        // layer 2
        float2 h2[HID];
#pragma unroll
        for (int m = 0; m < HID; m++) { float t = sB2[m]; h2[m] = make_float2(t, t); }
#pragma unroll
        for (int k = 0; k < HID; k++) {
            const float4* wr = reinterpret_cast<const float4*>(sW2 + k * HID);
            float2 hk = h1[k];
#pragma unroll
            for (int m4 = 0; m4 < 16; m4++) {
                float4 ww = wr[m4];
                fma2(h2[2 * m4 + 0], hk, make_float2(ww.x, ww.y));
                fma2(h2[2 * m4 + 1], hk, make_float2(ww.z, ww.w));
            }
        }
#pragma unroll
        for (int m = 0; m < HID; m++)
            acc[m] += fmaxf(h2[m].x, 0.f) + fmaxf(h2[m].y, 0.f);
    }

    // intra-warp butterfly reduce (all lanes end with full sums)
#pragma unroll
    for (int m = 0; m < HID; m++) {
#pragma unroll
        for (int o = 16; o > 0; o >>= 1)
            acc[m] += __shfl_xor_sync(0xffffffffu, acc[m], o);
    }
    int lane = tid & 31, warp = tid >> 5;
    sRed[warp * HID + lane] = acc[lane];
    __syncthreads();
    if (tid < HID) {
        float t = 0.f;
#pragma unroll
        for (int w = 0; w < NTHR / 32; w++) t += sRed[w * HID + tid];
        g_part[blockIdx.x * HID + tid] = t;
    }
}

// ---------------------------------------------------------------------------
// Phase 2: reduce block partials -> s[32]; head: out = relu(s@Wp+bp)@Wo + bo
// ---------------------------------------------------------------------------
__global__ void reduce_out(const float* __restrict__ Wp, const float* __restrict__ bp,
                           const float* __restrict__ Wo, const float* __restrict__ bo,
                           float* __restrict__ out) {
    __shared__ float tmp[8][HID];
    __shared__ float s[HID], pvec[HID];
    int tid = threadIdx.x;              // 256 threads
    int k = tid & 31, grp = tid >> 5;   // 8 groups of 32
    float lsum = 0.f;
    for (int b = grp; b < NBLK; b += 8)
        lsum += g_part[b * HID + k];
    tmp[grp][k] = lsum;
    __syncthreads();
    if (tid < HID) {
        float t = 0.f;
#pragma unroll
        for (int g = 0; g < 8; g++) t += tmp[g][tid];
        s[tid] = t;
    }
    __syncthreads();
    if (tid < HID) {
        float t = bp[tid];
#pragma unroll
        for (int kk = 0; kk < HID; kk++) t = fmaf(s[kk], Wp[kk * HID + tid], t);
        pvec[tid] = fmaxf(t, 0.f);
    }
    __syncthreads();
    if (tid < HID) {
        float t = bo[tid];
#pragma unroll
        for (int kk = 0; kk < HID; kk++) t = fmaf(pvec[kk], Wo[kk * HID + tid], t);
        out[tid] = t;
    }
}

// ---------------------------------------------------------------------------
extern "C" void kernel_launch(void* const* d_in, const int* in_sizes, int n_in,
                              void* d_out, int out_size) {
    const float* x  = (const float*)d_in[0];
    const float* W0 = (const float*)d_in[1];
    const float* b0 = (const float*)d_in[2];
    const float* W1 = (const float*)d_in[3];
    const float* b1 = (const float*)d_in[4];
    const float* W2 = (const float*)d_in[5];
    const float* b2 = (const float*)d_in[6];
    const float* Wp = (const float*)d_in[7];
    const float* bp = (const float*)d_in[8];
    const float* Wo = (const float*)d_in[9];
    const float* bo = (const float*)d_in[10];
    float* out = (float*)d_out;

    precompute_ab<<<(N_PIX * HID + 255) / 256, 256>>>(x, W0, b0);
    pair_kernel<<<NBLK, NTHR>>>(W1, b1, W2, b2);
    reduce_out<<<1, 256>>>(Wp, bp, Wo, bo, out);
}

// round 5
// speedup vs baseline: 1.3003x; 1.3003x over previous
#include <cuda_runtime.h>

// RelationalModule: inputs
//  0 x_img (64*40*40 f32)  1 W0 (130*32)  2 b0 (32)
//  3 W1 (32*32)  4 b1 (32)  5 W2 (32*32)  6 b2 (32)
//  7 Wp (32*32)  8 bp (32)  9 Wo (32*32) 10 bo (32)
// Output: 32 f32.

#define N_PIX 1600
#define CCH   64
#define HID   32
#define TI    32                 // i rows per tile
#define TJ    32                 // j rows per tile
#define TP    (TI * TJ)          // 1024 pairs per tile
#define NTI   (N_PIX / TI)       // 50
#define NTILE (NTI * NTI)        // 2500 blocks
#define NTHR  256

__device__ __align__(16) float g_a[N_PIX * HID];
__device__ __align__(16) float g_b[N_PIX * HID];    // includes +b0
__device__ __align__(16) float g_part[NTILE * HID];

// packed f32x2 FMA: acc.lo += a.lo*b.lo ; acc.hi += a.hi*b.hi
__device__ __forceinline__ void fma2(float2& acc, float2 a, float2 b) {
    asm volatile("fma.rn.f32x2 %0, %1, %2, %0;"
        : "+l"(reinterpret_cast<unsigned long long&>(acc))
        : "l"(reinterpret_cast<unsigned long long&>(a)),
          "l"(reinterpret_cast<unsigned long long&>(b)));
}

// ---------------------------------------------------------------------------
// Phase 0: per-pixel embeddings
// ---------------------------------------------------------------------------
__global__ void precompute_ab(const float* __restrict__ x,
                              const float* __restrict__ W0,
                              const float* __restrict__ b0) {
    int gid = blockIdx.x * blockDim.x + threadIdx.x;
    if (gid >= N_PIX * HID) return;
    int n = gid >> 5;
    int k = gid & 31;
    float fa = 0.f, fb = 0.f;
#pragma unroll 8
    for (int ch = 0; ch < CCH; ch++) {
        float xv = x[ch * N_PIX + n];
        fa = fmaf(xv, W0[ch * HID + k], fa);
        fb = fmaf(xv, W0[(CCH + 1 + ch) * HID + k], fb);
    }
    float cf = (float)n;
    fa = fmaf(cf, W0[CCH * HID + k], fa);
    fb = fmaf(cf, W0[(2 * CCH + 1) * HID + k], fb);
    g_a[gid] = fa;
    g_b[gid] = fb + b0[k];
}

// ---------------------------------------------------------------------------
// GEMM-like layer: acc[m][q] (+= bias) accumulates over k from H[k][p] tile.
// Each thread: 8 pairs (4 float2 chunks strided 256 pairs) x 16 outputs.
// Weights pre-duplicated {w,w}: one LDS.128 broadcast feeds 8 fma2.
// ---------------------------------------------------------------------------
__device__ __forceinline__ void run_layer(const float* __restrict__ H,
                                          const float2* __restrict__ Wd,
                                          const float2* __restrict__ bd,
                                          int pbyte, int mgrp,
                                          float2 acc[16][4]) {
#pragma unroll
    for (int m = 0; m < 16; m++) {
        float2 bv = bd[mgrp * 16 + m];
#pragma unroll
        for (int q = 0; q < 4; q++) acc[m][q] = bv;
    }
#pragma unroll 4
    for (int k = 0; k < 32; k++) {
        float2 pv[4];
        const char* rowp = (const char*)(H + k * TP) + pbyte;
#pragma unroll
        for (int q = 0; q < 4; q++)
            pv[q] = *(const float2*)(rowp + q * 1024);
        const float4* wr = (const float4*)(Wd + k * HID + mgrp * 16);
#pragma unroll
        for (int m4 = 0; m4 < 8; m4++) {
            float4 wf = wr[m4];
            float2 w0 = make_float2(wf.x, wf.y);
            float2 w1 = make_float2(wf.z, wf.w);
#pragma unroll
            for (int q = 0; q < 4; q++) fma2(acc[2 * m4 + 0][q], pv[q], w0);
#pragma unroll
            for (int q = 0; q < 4; q++) fma2(acc[2 * m4 + 1][q], pv[q], w1);
        }
    }
}

// ---------------------------------------------------------------------------
// Phase 1: tiled pair MLP. Grid = 2500 tiles of 32 i x 32 j.
// ---------------------------------------------------------------------------
__global__ void __launch_bounds__(NTHR, 1)
pair_kernel(const float* __restrict__ W1, const float* __restrict__ b1,
            const float* __restrict__ W2, const float* __restrict__ b2) {
    extern __shared__ __align__(16) float smem[];
    float*  H    = smem;                          // [32][1024]
    float2* W1d  = (float2*)(H + 32 * TP);        // [32][32] dup
    float2* W2d  = W1d + HID * HID;
    float*  a_s  = (float*)(W2d + HID * HID);     // [32][33] padded
    float*  b_s  = a_s + TJ * 33;                 // [32][32]
    float2* b1d  = (float2*)(b_s + TI * HID);
    float2* b2d  = b1d + HID;
    float*  sred = (float*)(b2d + HID);           // [8][32]

    int tid = threadIdx.x;
    int blk = blockIdx.x;
    int i0 = (blk / NTI) * TI;
    int j0 = (blk % NTI) * TJ;

    // prep: duplicated weights + biases; zero sred (only half is written later,
    // the other half must be 0 on EVERY launch, incl. graph replays)
    sred[tid] = 0.f;
    for (int idx = tid; idx < HID * HID; idx += NTHR) {
        float w1 = W1[idx]; W1d[idx] = make_float2(w1, w1);
        float w2 = W2[idx]; W2d[idx] = make_float2(w2, w2);
    }
    if (tid < HID) {
        float v1 = b1[tid]; b1d[tid] = make_float2(v1, v1);
        float v2 = b2[tid]; b2d[tid] = make_float2(v2, v2);
    }
    // stage a (padded rows for conflict-free transposed reads) and b (raw)
    {
        int row = tid >> 3, c4 = (tid & 7) * 4;
        float4 av = *(const float4*)(g_a + (j0 + row) * HID + c4);
        a_s[row * 33 + c4 + 0] = av.x;
        a_s[row * 33 + c4 + 1] = av.y;
        a_s[row * 33 + c4 + 2] = av.z;
        a_s[row * 33 + c4 + 3] = av.w;
        float4 bv = *(const float4*)(g_b + (i0 + row) * HID + c4);
        *(float4*)(b_s + row * HID + c4) = bv;
    }
    __syncthreads();

    // phase A: H0[k][p] = relu(a[j][k] + b[i][k]), p = ii*32 + jj
#pragma unroll
    for (int rep = 0; rep < 4; rep++) {
        int p = rep * NTHR + tid;
        int ii = p >> 5, jj = p & 31;
        const float* ar = a_s + jj * 33;
        const float* br = b_s + ii * HID;
#pragma unroll 8
        for (int k = 0; k < 32; k++)
            H[k * TP + p] = fmaxf(ar[k] + br[k], 0.f);
    }
    __syncthreads();

    int pgrp = tid & 127;          // 128 pair-groups: 2 consecutive pairs x 4 chunks
    int mgrp = tid >> 7;           // 2 output-halves (warp-uniform)
    int pbyte = pgrp * 8;          // byte offset of this thread's first float2

    float2 acc[16][4];

    // layer 1
    run_layer(H, W1d, b1d, pbyte, mgrp, acc);
    __syncthreads();               // all H0 reads done before overwrite
#pragma unroll
    for (int m = 0; m < 16; m++) {
        char* rowp = (char*)(H + (mgrp * 16 + m) * TP) + pbyte;
#pragma unroll
        for (int q = 0; q < 4; q++) {
            float2 r = make_float2(fmaxf(acc[m][q].x, 0.f), fmaxf(acc[m][q].y, 0.f));
            *(float2*)(rowp + q * 1024) = r;
        }
    }
    __syncthreads();

    // layer 2
    run_layer(H, W2d, b2d, pbyte, mgrp, acc);

    // final relu + per-thread pair-sum
    float s[16];
#pragma unroll
    for (int m = 0; m < 16; m++) {
        float t = 0.f;
#pragma unroll
        for (int q = 0; q < 4; q++)
            t += fmaxf(acc[m][q].x, 0.f) + fmaxf(acc[m][q].y, 0.f);
        s[m] = t;
    }
    // warp butterfly: lanes cover disjoint pairs, same mgrp
#pragma unroll
    for (int m = 0; m < 16; m++) {
#pragma unroll
        for (int o = 16; o > 0; o >>= 1)
            s[m] += __shfl_xor_sync(0xffffffffu, s[m], o);
    }
    int lane = tid & 31, wrp = tid >> 5;
    if (lane < 16) sred[wrp * HID + mgrp * 16 + lane] = s[lane];
    __syncthreads();
    if (tid < HID) {
        float t = 0.f;
#pragma unroll
        for (int w = 0; w < 8; w++) t += sred[w * HID + tid];
        g_part[blk * HID + tid] = t;
    }
}

// ---------------------------------------------------------------------------
// Phase 2: reduce 2500 partials -> s[32]; head MLP -> out[32]
// ---------------------------------------------------------------------------
__global__ void reduce_out(const float* __restrict__ Wp, const float* __restrict__ bp,
                           const float* __restrict__ Wo, const float* __restrict__ bo,
                           float* __restrict__ out) {
    __shared__ float tmp[8][HID];
    __shared__ float s[HID], pvec[HID];
    int tid = threadIdx.x;              // 256
    int k = tid & 31, grp = tid >> 5;
    float lsum = 0.f;
    for (int b = grp; b < NTILE; b += 8)
        lsum += g_part[b * HID + k];
    tmp[grp][k] = lsum;
    __syncthreads();
    if (tid < HID) {
        float t = 0.f;
#pragma unroll
        for (int g = 0; g < 8; g++) t += tmp[g][tid];
        s[tid] = t;
    }
    __syncthreads();
    if (tid < HID) {
        float t = bp[tid];
#pragma unroll
        for (int kk = 0; kk < HID; kk++) t = fmaf(s[kk], Wp[kk * HID + tid], t);
        pvec[tid] = fmaxf(t, 0.f);
    }
    __syncthreads();
    if (tid < HID) {
        float t = bo[tid];
#pragma unroll
        for (int kk = 0; kk < HID; kk++) t = fmaf(pvec[kk], Wo[kk * HID + tid], t);
        out[tid] = t;
    }
}

// ---------------------------------------------------------------------------
extern "C" void kernel_launch(void* const* d_in, const int* in_sizes, int n_in,
                              void* d_out, int out_size) {
    const float* x  = (const float*)d_in[0];
    const float* W0 = (const float*)d_in[1];
    const float* b0 = (const float*)d_in[2];
    const float* W1 = (const float*)d_in[3];
    const float* b1 = (const float*)d_in[4];
    const float* W2 = (const float*)d_in[5];
    const float* b2 = (const float*)d_in[6];
    const float* Wp = (const float*)d_in[7];
    const float* bp = (const float*)d_in[8];
    const float* Wo = (const float*)d_in[9];
    const float* bo = (const float*)d_in[10];
    float* out = (float*)d_out;

    // dynamic smem: H 128KB + Wdup 16KB + a_s/b_s + biases + sred
    static int smem_set = 0;
    int smem_bytes = (32 * TP + 2 * HID * HID * 2 + TJ * 33 + TI * HID
                      + 2 * HID * 2 + 8 * HID) * (int)sizeof(float);
    if (!smem_set) {
        cudaFuncSetAttribute(pair_kernel,
                             cudaFuncAttributeMaxDynamicSharedMemorySize, smem_bytes);
        smem_set = 1;
    }

    precompute_ab<<<(N_PIX * HID + 255) / 256, 256>>>(x, W0, b0);
    pair_kernel<<<NTILE, NTHR, smem_bytes>>>(W1, b1, W2, b2);
    reduce_out<<<1, 256>>>(Wp, bp, Wo, bo, out);
}

// round 7
// speedup vs baseline: 3.5800x; 2.7532x over previous
#include <cuda_runtime.h>
#include <cstdint>

// RelationalModule via warp-level mma.sync m16n8k16 bf16 with hi/lo split.
// Inputs: 0 x_img(64*1600) 1 W0(130*32) 2 b0 3 W1 4 b1 5 W2 6 b2 7 Wp 8 bp 9 Wo 10 bo
// Output: 32 f32.

#define N_PIX 1600
#define HID   32
#define NJT   (N_PIX / 32)          // 50 j-tiles
#define NUNIT (NJT * N_PIX)         // 80,000 units (1 i x 32 j each)
#define NCTA  296
#define WPC   4                     // warps per CTA (128 threads)
#define NW    (NCTA * WPC)          // 1184 warps

__device__ __align__(16) float g_a[N_PIX * HID];   // [n][k]
__device__ __align__(16) float g_b[N_PIX * HID];   // [n][k], includes +b0
__device__ __align__(16) float g_part[NW * HID];

// ---------------------------------------------------------------------------
// helpers
// ---------------------------------------------------------------------------
// pack (x0 -> low bf16, x1 -> high bf16) rounding-to-nearest, plus residual pack
__device__ __forceinline__ void splitpair(float x0, float x1,
                                          uint32_t& hi, uint32_t& lo) {
    uint32_t h;
    asm("cvt.rn.bf16x2.f32 %0, %1, %2;" : "=r"(h) : "f"(x1), "f"(x0));
    float r0 = __uint_as_float(h << 16);
    float r1 = __uint_as_float(h & 0xffff0000u);
    float d0 = x0 - r0, d1 = x1 - r1;
    uint32_t l;
    asm("cvt.rn.bf16x2.f32 %0, %1, %2;" : "=r"(l) : "f"(d1), "f"(d0));
    hi = h; lo = l;
}

__device__ __forceinline__ void mma16816(float* d, const uint32_t* a,
                                         const uint32_t* b) {
    asm("mma.sync.aligned.m16n8k16.row.col.f32.bf16.bf16.f32 "
        "{%0,%1,%2,%3}, {%4,%5,%6,%7}, {%8,%9}, {%0,%1,%2,%3};"
        : "+f"(d[0]), "+f"(d[1]), "+f"(d[2]), "+f"(d[3])
        : "r"(a[0]), "r"(a[1]), "r"(a[2]), "r"(a[3]), "r"(b[0]), "r"(b[1]));
}

// ---------------------------------------------------------------------------
// Phase 0: per-pixel embeddings, [n][k] layout; g_b includes +b0
// ---------------------------------------------------------------------------
__global__ void precompute_ab(const float* __restrict__ x,
                              const float* __restrict__ W0,
                              const float* __restrict__ b0) {
    int gid = blockIdx.x * blockDim.x + threadIdx.x;
    if (gid >= N_PIX * HID) return;
    int n = gid >> 5;
    int k = gid & 31;
    float fa = 0.f, fb = 0.f;
#pragma unroll 8
    for (int ch = 0; ch < 64; ch++) {
        float xv = x[ch * N_PIX + n];
        fa = fmaf(xv, W0[ch * HID + k], fa);
        fb = fmaf(xv, W0[(65 + ch) * HID + k], fb);
    }
    float cf = (float)n;
    fa = fmaf(cf, W0[64 * HID + k], fa);
    fb = fmaf(cf, W0[129 * HID + k], fb);
    g_a[gid] = fa;
    g_b[gid] = fb + b0[k];
}

// ---------------------------------------------------------------------------
// Phase 1: pair MLP on tensor cores (mma.sync).
// Unit = 1 i x 32 j pairs. M=32 (2 m16 tiles), N=32 (4 n8 tiles),
// K' = 96 = [hi(32) | lo(32) | hi(32)] against [Whi | Whi | Wlo].
// ---------------------------------------------------------------------------
__global__ void __launch_bounds__(128)
pair_kernel(const float* __restrict__ W1, const float* __restrict__ b1,
            const float* __restrict__ W2, const float* __restrict__ b2) {
    int lane = threadIdx.x & 31;
    int warp = threadIdx.x >> 5;
    int g = lane >> 2;              // 0..7
    int t = lane & 3;               // 0..3
    int w = blockIdx.x * WPC + warp;

    // ---- B fragments (both layers, hi+lo), in registers ----
    // b-frag reg packing: low bf16 = B[k_even][n], high = B[k_even+1][n]
    uint32_t B1h[2][4][2], B1l[2][4][2], B2h[2][4][2], B2l[2][4][2];
#pragma unroll
    for (int kbk = 0; kbk < 2; kbk++)
#pragma unroll
        for (int nt = 0; nt < 4; nt++)
#pragma unroll
            for (int r = 0; r < 2; r++) {
                int n = 8 * nt + g;
                int k0 = kbk * 16 + r * 8 + 2 * t;
                splitpair(W1[k0 * HID + n], W1[(k0 + 1) * HID + n],
                          B1h[kbk][nt][r], B1l[kbk][nt][r]);
                splitpair(W2[k0 * HID + n], W2[(k0 + 1) * HID + n],
                          B2h[kbk][nt][r], B2l[kbk][nt][r]);
            }
    // biases at this lane's accumulator columns (cols 8nt+2t, 8nt+2t+1)
    float bias1[8], bias2[8];
#pragma unroll
    for (int nt = 0; nt < 4; nt++) {
        bias1[2 * nt + 0] = b1[8 * nt + 2 * t];
        bias1[2 * nt + 1] = b1[8 * nt + 2 * t + 1];
        bias2[2 * nt + 0] = b2[8 * nt + 2 * t];
        bias2[2 * nt + 1] = b2[8 * nt + 2 * t + 1];
    }

    float accE[4], accO[4];
#pragma unroll
    for (int nt = 0; nt < 4; nt++) { accE[nt] = 0.f; accO[nt] = 0.f; }

    const float2* ga2 = (const float2*)g_a;
    const float2* gb2 = (const float2*)g_b;

    long long u0l = ((long long)w * NUNIT) / NW;
    long long u1l = ((long long)(w + 1) * NUNIT) / NW;
    int u0 = (int)u0l, u1 = (int)u1l;
    int jt = u0 / N_PIX;
    int i  = u0 - jt * N_PIX;

    for (int u = u0; u < u1; u++) {
        int j0 = jt * 32;
        // b row float2s this lane needs: k = 8*kk + 2t
        float2 bv[4];
#pragma unroll
        for (int kk = 0; kk < 4; kk++)
            bv[kk] = gb2[i * 16 + kk * 4 + t];

        // ---- build h0 A-fragments (hi/lo) ----
        uint32_t Ah[2][2][4], Al[2][2][4];
#pragma unroll
        for (int mt = 0; mt < 2; mt++) {
            int ra = j0 + mt * 16 + g;
            int rb = ra + 8;
#pragma unroll
            for (int kbk = 0; kbk < 2; kbk++)
#pragma unroll
                for (int half = 0; half < 2; half++) {
                    int fidx = kbk * 8 + half * 4 + t;
                    float2 a0v = ga2[ra * 16 + fidx];
                    float2 a1v = ga2[rb * 16 + fidx];
                    float2 b = bv[kbk * 2 + half];
                    float h00 = fmaxf(a0v.x + b.x, 0.f);
                    float h01 = fmaxf(a0v.y + b.y, 0.f);
                    float h10 = fmaxf(a1v.x + b.x, 0.f);
                    float h11 = fmaxf(a1v.y + b.y, 0.f);
                    splitpair(h00, h01, Ah[mt][kbk][half * 2 + 0],
                                        Al[mt][kbk][half * 2 + 0]);
                    splitpair(h10, h11, Ah[mt][kbk][half * 2 + 1],
                                        Al[mt][kbk][half * 2 + 1]);
                }
        }

        // ---- layer 1 ----
        float D[2][4][4];
#pragma unroll
        for (int mt = 0; mt < 2; mt++)
#pragma unroll
            for (int nt = 0; nt < 4; nt++) {
                D[mt][nt][0] = bias1[2 * nt];     D[mt][nt][1] = bias1[2 * nt + 1];
                D[mt][nt][2] = bias1[2 * nt];     D[mt][nt][3] = bias1[2 * nt + 1];
            }
#pragma unroll
        for (int mt = 0; mt < 2; mt++)
#pragma unroll
            for (int nt = 0; nt < 4; nt++) {
                mma16816(D[mt][nt], Ah[mt][0], B1h[0][nt]);
                mma16816(D[mt][nt], Ah[mt][1], B1h[1][nt]);
                mma16816(D[mt][nt], Al[mt][0], B1h[0][nt]);
                mma16816(D[mt][nt], Al[mt][1], B1h[1][nt]);
                mma16816(D[mt][nt], Ah[mt][0], B1l[0][nt]);
                mma16816(D[mt][nt], Ah[mt][1], B1l[1][nt]);
            }

        // ---- h1 = relu(D1) -> A fragments (C->A layout identity) ----
#pragma unroll
        for (int mt = 0; mt < 2; mt++)
#pragma unroll
            for (int kbk = 0; kbk < 2; kbk++) {
                int n0 = 2 * kbk, n1 = 2 * kbk + 1;
                splitpair(fmaxf(D[mt][n0][0], 0.f), fmaxf(D[mt][n0][1], 0.f),
                          Ah[mt][kbk][0], Al[mt][kbk][0]);
                splitpair(fmaxf(D[mt][n0][2], 0.f), fmaxf(D[mt][n0][3], 0.f),
                          Ah[mt][kbk][1], Al[mt][kbk][1]);
                splitpair(fmaxf(D[mt][n1][0], 0.f), fmaxf(D[mt][n1][1], 0.f),
                          Ah[mt][kbk][2], Al[mt][kbk][2]);
                splitpair(fmaxf(D[mt][n1][2], 0.f), fmaxf(D[mt][n1][3], 0.f),
                          Ah[mt][kbk][3], Al[mt][kbk][3]);
            }

        // ---- layer 2 ----
#pragma unroll
        for (int mt = 0; mt < 2; mt++)
#pragma unroll
            for (int nt = 0; nt < 4; nt++) {
                D[mt][nt][0] = bias2[2 * nt];     D[mt][nt][1] = bias2[2 * nt + 1];
                D[mt][nt][2] = bias2[2 * nt];     D[mt][nt][3] = bias2[2 * nt + 1];
            }
#pragma unroll
        for (int mt = 0; mt < 2; mt++)
#pragma unroll
            for (int nt = 0; nt < 4; nt++) {
                mma16816(D[mt][nt], Ah[mt][0], B2h[0][nt]);
                mma16816(D[mt][nt], Ah[mt][1], B2h[1][nt]);
                mma16816(D[mt][nt], Al[mt][0], B2h[0][nt]);
                mma16816(D[mt][nt], Al[mt][1], B2h[1][nt]);
                mma16816(D[mt][nt], Ah[mt][0], B2l[0][nt]);
                mma16816(D[mt][nt], Ah[mt][1], B2l[1][nt]);
            }

        // ---- acc += relu(D2), rows folded ----
#pragma unroll
        for (int nt = 0; nt < 4; nt++) {
            accE[nt] += fmaxf(D[0][nt][0], 0.f) + fmaxf(D[0][nt][2], 0.f)
                      + fmaxf(D[1][nt][0], 0.f) + fmaxf(D[1][nt][2], 0.f);
            accO[nt] += fmaxf(D[0][nt][1], 0.f) + fmaxf(D[0][nt][3], 0.f)
                      + fmaxf(D[1][nt][1], 0.f) + fmaxf(D[1][nt][3], 0.f);
        }

        // advance unit
        if (++i == N_PIX) { i = 0; jt++; }
    }

    // ---- reduce over the 8 g-groups (t stays fixed) ----
#pragma unroll
    for (int nt = 0; nt < 4; nt++) {
#pragma unroll
        for (int o = 4; o < 32; o <<= 1) {
            accE[nt] += __shfl_xor_sync(0xffffffffu, accE[nt], o);
            accO[nt] += __shfl_xor_sync(0xffffffffu, accO[nt], o);
        }
    }
    if (lane < 4) {   // g==0 lanes, t = lane
#pragma unroll
        for (int nt = 0; nt < 4; nt++) {
            g_part[w * HID + 8 * nt + 2 * lane + 0] = accE[nt];
            g_part[w * HID + 8 * nt + 2 * lane + 1] = accO[nt];
        }
    }
}

// ---------------------------------------------------------------------------
// Phase 2: reduce 1184 partials -> s[32]; head MLP -> out[32]
// ---------------------------------------------------------------------------
__global__ void reduce_out(const float* __restrict__ Wp, const float* __restrict__ bp,
                           const float* __restrict__ Wo, const float* __restrict__ bo,
                           float* __restrict__ out) {
    __shared__ float tmp[8][HID];
    __shared__ float s[HID], pvec[HID];
    int tid = threadIdx.x;              // 256
    int k = tid & 31, grp = tid >> 5;
    float lsum = 0.f;
    for (int b = grp; b < NW; b += 8)
        lsum += g_part[b * HID + k];
    tmp[grp][k] = lsum;
    __syncthreads();
    if (tid < HID) {
        float t = 0.f;
#pragma unroll
        for (int gg = 0; gg < 8; gg++) t += tmp[gg][tid];
        s[tid] = t;
    }
    __syncthreads();
    if (tid < HID) {
        float t = bp[tid];
#pragma unroll
        for (int kk = 0; kk < HID; kk++) t = fmaf(s[kk], Wp[kk * HID + tid], t);
        pvec[tid] = fmaxf(t, 0.f);
    }
    __syncthreads();
    if (tid < HID) {
        float t = bo[tid];
#pragma unroll
        for (int kk = 0; kk < HID; kk++) t = fmaf(pvec[kk], Wo[kk * HID + tid], t);
        out[tid] = t;
    }
}

// ---------------------------------------------------------------------------
extern "C" void kernel_launch(void* const* d_in, const int* in_sizes, int n_in,
                              void* d_out, int out_size) {
    const float* x  = (const float*)d_in[0];
    const float* W0 = (const float*)d_in[1];
    const float* b0 = (const float*)d_in[2];
    const float* W1 = (const float*)d_in[3];
    const float* b1 = (const float*)d_in[4];
    const float* W2 = (const float*)d_in[5];
    const float* b2 = (const float*)d_in[6];
    const float* Wp = (const float*)d_in[7];
    const float* bp = (const float*)d_in[8];
    const float* Wo = (const float*)d_in[9];
    const float* bo = (const float*)d_in[10];
    float* out = (float*)d_out;

    precompute_ab<<<(N_PIX * HID + 255) / 256, 256>>>(x, W0, b0);
    pair_kernel<<<NCTA, 128>>>(W1, b1, W2, b2);
    reduce_out<<<1, 256>>>(Wp, bp, Wo, bo, out);
}